// round 2
// baseline (speedup 1.0000x reference)
#include <cuda_runtime.h>

// MDN_module, fully fused single kernel.
// Inputs: x[B,2] y[B,1,2] eps[B,1,2] W1[2,64] b1[64] W2[64,4] b2[4] Wv[2,2]
// Output: fx (2B floats) then logp_y scalar at out[2B].

#define HID 64
#define PAIRS 4            // row-pairs per thread per group (8 rows/group)
#define NTHREADS 256
#define MAXBLK 512

__device__ double g_part[MAXBLK];
__device__ unsigned g_ticket = 0;

// packed f32x2 FMA on float2; single asm block so ptxas coalesces the movs
__device__ __forceinline__ float2 ffma2(float2 a, float2 b, float2 c) {
    float2 d;
    asm("{\n\t"
        ".reg .b64 ra, rb, rc, rd;\n\t"
        "mov.b64 ra, {%2, %3};\n\t"
        "mov.b64 rb, {%4, %5};\n\t"
        "mov.b64 rc, {%6, %7};\n\t"
        "fma.rn.f32x2 rd, ra, rb, rc;\n\t"
        "mov.b64 {%0, %1}, rd;\n\t"
        "}"
        : "=f"(d.x), "=f"(d.y)
        : "f"(a.x), "f"(a.y), "f"(b.x), "f"(b.y), "f"(c.x), "f"(c.y));
    return d;
}

// per-row epilogue: returns d0^2/v0 + d1^2/v1 + f2 + f3 ; writes fx0,fx1
__device__ __forceinline__ float row_tail(
    float x0, float x1, float mu0, float mu1, float f2, float f3,
    float y0, float y1, float e0, float e1,
    float wv00, float wv01, float wv10, float wv11,
    float& fx0, float& fx1)
{
    float z0 = fmaf(x0, wv00, x1 * wv10);
    float z1 = fmaf(x0, wv01, x1 * wv11);
    float Vx = fmaf(z0, z0, fmaf(z1, z1, 1e-3f));
    float m0 = fmaf(mu0, wv00, mu1 * wv10);
    float m1 = fmaf(mu0, wv01, mu1 * wv11);
    float Vmu = fmaf(m0, m0, fmaf(m1, m1, 1e-3f));
    float scale = fminf(0.99f * Vx, Vmu) / Vmu;   // == beta*Vx - relu(beta*Vx - Vmu), /Vmu
    float ms0 = mu0 * scale;
    float ms1 = mu1 * scale;
    float v0 = __expf(f2);
    float v1 = __expf(f3);
    float r0 = rsqrtf(v0);
    float r1 = rsqrtf(v1);
    fx0 = fmaf(v0 * r0, e0, ms0);
    fx1 = fmaf(v1 * r1, e1, ms1);
    float d0 = y0 - ms0;
    float d1 = y1 - ms1;
    float s = fmaf(d0 * d0, r0 * r0, f2 + f3);    // log v0 + log v1 == f2 + f3 exactly
    s = fmaf(d1 * d1, r1 * r1, s);
    return s;
}

__global__ void __launch_bounds__(NTHREADS, 2)
mdn_fused(const float4* __restrict__ x4, const float4* __restrict__ y4,
          const float4* __restrict__ e4,
          const float* __restrict__ W1, const float* __restrict__ b1,
          const float* __restrict__ W2, const float* __restrict__ b2,
          const float* __restrict__ Wv,
          float4* __restrict__ o4, float* __restrict__ out,
          int nGroups, long long B)
{
    // per-neuron packed weights: q0={w0,w0,w1,w1} q1={b,b,c0,c0} q2={c1,c1,c2,c2} q3={c3,c3,-,-}
    __shared__ float4 swq[HID][4];
    __shared__ double sred[NTHREADS];

    int t = threadIdx.x;
    if (t < HID) {
        float w0 = W1[t], w1 = W1[HID + t], b = b1[t];
        float c0 = W2[t * 4 + 0], c1 = W2[t * 4 + 1];
        float c2 = W2[t * 4 + 2], c3 = W2[t * 4 + 3];
        swq[t][0] = make_float4(w0, w0, w1, w1);
        swq[t][1] = make_float4(b, b, c0, c0);
        swq[t][2] = make_float4(c1, c1, c2, c2);
        swq[t][3] = make_float4(c3, c3, 0.f, 0.f);
    }
    __syncthreads();

    float wv00 = Wv[0], wv01 = Wv[1], wv10 = Wv[2], wv11 = Wv[3];
    float2 pb2_0 = make_float2(b2[0], b2[0]);
    float2 pb2_1 = make_float2(b2[1], b2[1]);
    float2 pb2_2 = make_float2(b2[2], b2[2]);
    float2 pb2_3 = make_float2(b2[3], b2[3]);

    float lsum = 0.0f;
    int tid = blockIdx.x * blockDim.x + threadIdx.x;
    int stride = gridDim.x * blockDim.x;

    for (int g = tid; g < nGroups; g += stride) {
        int base = g * PAIRS;
        float2 X0[PAIRS], X1[PAIRS];
        float2 a0[PAIRS], a1[PAIRS], a2[PAIRS], a3[PAIRS];
#pragma unroll
        for (int p = 0; p < PAIRS; p++) {
            float4 xv = x4[base + p];              // {x0_a, x1_a, x0_b, x1_b}
            X0[p] = make_float2(xv.x, xv.z);
            X1[p] = make_float2(xv.y, xv.w);
            a0[p] = pb2_0; a1[p] = pb2_1; a2[p] = pb2_2; a3[p] = pb2_3;
        }

#pragma unroll 4
        for (int j = 0; j < HID; j++) {
            float4 q0 = swq[j][0];
            float4 q1 = swq[j][1];
            float4 q2 = swq[j][2];
            float4 q3 = swq[j][3];
            float2 w0 = make_float2(q0.x, q0.y), w1 = make_float2(q0.z, q0.w);
            float2 bb = make_float2(q1.x, q1.y), c0 = make_float2(q1.z, q1.w);
            float2 c1 = make_float2(q2.x, q2.y), c2 = make_float2(q2.z, q2.w);
            float2 c3 = make_float2(q3.x, q3.y);
#pragma unroll
            for (int p = 0; p < PAIRS; p++) {
                float2 pre = ffma2(X1[p], w1, bb);
                pre = ffma2(X0[p], w0, pre);
                pre.x = fmaxf(pre.x, 0.0f);        // FMNMX on the pair halves, no repack
                pre.y = fmaxf(pre.y, 0.0f);
                a0[p] = ffma2(pre, c0, a0[p]);
                a1[p] = ffma2(pre, c1, a1[p]);
                a2[p] = ffma2(pre, c2, a2[p]);
                a3[p] = ffma2(pre, c3, a3[p]);
            }
        }

#pragma unroll
        for (int p = 0; p < PAIRS; p++) {
            float4 yv = y4[base + p];
            float4 ev = e4[base + p];
            float fa0, fa1, fb0, fb1;
            lsum += row_tail(X0[p].x, X1[p].x, a0[p].x, a1[p].x, a2[p].x, a3[p].x,
                             yv.x, yv.y, ev.x, ev.y,
                             wv00, wv01, wv10, wv11, fa0, fa1);
            lsum += row_tail(X0[p].y, X1[p].y, a0[p].y, a1[p].y, a2[p].y, a3[p].y,
                             yv.z, yv.w, ev.z, ev.w,
                             wv00, wv01, wv10, wv11, fb0, fb1);
            float4 o; o.x = fa0; o.y = fa1; o.z = fb0; o.w = fb1;
            o4[base + p] = o;
        }
    }

    // tail rows not covered by 8-row groups: block 0 handles scalar
    long long startRow = (long long)nGroups * 8;
    if (blockIdx.x == 0 && startRow + threadIdx.x < B) {
        long long r = startRow + threadIdx.x;
        const float* x = (const float*)x4;
        const float* y = (const float*)y4;
        const float* e = (const float*)e4;
        float x0 = x[2 * r], x1 = x[2 * r + 1];
        float f0 = b2[0], f1 = b2[1], f2 = b2[2], f3 = b2[3];
        for (int j = 0; j < HID; j++) {
            float h = fmaxf(fmaf(x0, W1[j], fmaf(x1, W1[HID + j], b1[j])), 0.0f);
            f0 = fmaf(h, W2[j * 4 + 0], f0);
            f1 = fmaf(h, W2[j * 4 + 1], f1);
            f2 = fmaf(h, W2[j * 4 + 2], f2);
            f3 = fmaf(h, W2[j * 4 + 3], f3);
        }
        float fx0, fx1;
        lsum += row_tail(x0, x1, f0, f1, f2, f3,
                         y[2 * r], y[2 * r + 1], e[2 * r], e[2 * r + 1],
                         wv00, wv01, wv10, wv11, fx0, fx1);
        ((float*)o4)[2 * r] = fx0;
        ((float*)o4)[2 * r + 1] = fx1;
    }

    // block reduction (deterministic tree) -> per-block double partial
    sred[threadIdx.x] = (double)lsum;
    __syncthreads();
#pragma unroll
    for (int off = NTHREADS / 2; off > 0; off >>= 1) {
        if (threadIdx.x < off) sred[threadIdx.x] += sred[threadIdx.x + off];
        __syncthreads();
    }
    if (threadIdx.x == 0) g_part[blockIdx.x] = sred[0];

    // last-block finalize (threadfence reduction pattern)
    __shared__ bool is_last;
    __threadfence();
    if (threadIdx.x == 0) {
        unsigned prev = atomicAdd(&g_ticket, 1u);
        is_last = (prev == gridDim.x - 1);
    }
    __syncthreads();
    if (is_last) {
        double v = 0.0;
        for (int i = threadIdx.x; i < gridDim.x; i += NTHREADS) v += g_part[i];
        sred[threadIdx.x] = v;
        __syncthreads();
#pragma unroll
        for (int off = NTHREADS / 2; off > 0; off >>= 1) {
            if (threadIdx.x < off) sred[threadIdx.x] += sred[threadIdx.x + off];
            __syncthreads();
        }
        if (threadIdx.x == 0) {
            out[2 * B] = (float)(0.5 * sred[0] + (double)B * 1.8378770664093453);
            g_ticket = 0;   // reset for next graph replay
        }
    }
}

extern "C" void kernel_launch(void* const* d_in, const int* in_sizes, int n_in,
                              void* d_out, int out_size)
{
    const float* x  = (const float*)d_in[0];
    const float* y  = (const float*)d_in[1];
    const float* e  = (const float*)d_in[2];
    const float* W1 = (const float*)d_in[3];
    const float* b1 = (const float*)d_in[4];
    const float* W2 = (const float*)d_in[5];
    const float* b2 = (const float*)d_in[6];
    const float* Wv = (const float*)d_in[7];
    float* out = (float*)d_out;

    long long B = (long long)in_sizes[0] / 2;
    int nGroups = (int)(B / 8);

    int blocks = 304;                    // ~2 per SM, persistent grid-stride
    if (blocks > MAXBLK) blocks = MAXBLK;

    mdn_fused<<<blocks, NTHREADS>>>((const float4*)x, (const float4*)y,
                                    (const float4*)e, W1, b1, W2, b2, Wv,
                                    (float4*)out, out, nGroups, B);
}